// round 3
// baseline (speedup 1.0000x reference)
#include <cuda_runtime.h>

#define EDIM 64
#define NDIM 128
#define MAXNODES 65536
#define TILE 8
#define THREADS 128
#define LN_EPS 1e-5f

__device__ float g_degree[MAXNODES];

__global__ void zero_kernel(float4* __restrict__ out, int n_out4, int n_nodes) {
    int i = blockIdx.x * blockDim.x + threadIdx.x;
    int stride = gridDim.x * blockDim.x;
    float4 z = make_float4(0.f, 0.f, 0.f, 0.f);
    for (int j = i; j < n_out4; j += stride) out[j] = z;
    for (int j = i; j < n_nodes; j += stride) g_degree[j] = 0.f;
}

__global__ __launch_bounds__(THREADS, 4) void edge_kernel(
    const float* __restrict__ edge_attr,
    const float* __restrict__ W,
    const float* __restrict__ b,
    const float* __restrict__ gamma,
    const float* __restrict__ beta,
    const int* __restrict__ eidx,          // int32! (JAX x64 disabled)
    float* __restrict__ out,
    int E, int n_nodes)
{
    __shared__ __align__(16) float sa[TILE][EDIM];   // staged edge attrs
    __shared__ __align__(16) float sh[TILE][NDIM];   // normalized edge features
    __shared__ float sred[TILE][2][4];               // per-warp partials (sum, sumsq)
    __shared__ int sidx[2][TILE];                    // endpoints

    const int tid  = threadIdx.x;
    const int lane = tid & 31;
    const int warp = tid >> 5;
    const int c    = tid;                            // output channel of this thread

    // W column in registers: W is [EDIM][NDIM] row-major -> coalesced loads
    float Wreg[EDIM];
#pragma unroll
    for (int k = 0; k < EDIM; k++) Wreg[k] = W[k * NDIM + c];
    const float bc  = b[c];
    const float gc  = gamma[c];
    const float bec = beta[c];

    const int n_tiles = (E + TILE - 1) / TILE;

    for (int t0 = blockIdx.x; t0 < n_tiles; t0 += gridDim.x) {
        const int e0 = t0 * TILE;
        const int nE = min(TILE, E - e0);

        // ---- stage edge tile: TILE*EDIM/4 = 128 float4, one per thread ----
        {
            const int e  = tid >> 4;          // 0..7
            const int k4 = tid & 15;          // 0..15
            if (e < nE) {
                ((float4*)sa[e])[k4] =
                    ((const float4*)(edge_attr + (long long)(e0 + e) * EDIM))[k4];
            }
        }
        if (tid < 2 * TILE) {
            const int which = tid / TILE;     // 0 = row0, 1 = row1 of edge_index
            const int e     = tid % TILE;
            sidx[which][e] = (e < nE) ? eidx[which * E + e0 + e] : 0;
        }
        __syncthreads();

        // ---- linear + relu + warp partial reductions ----
        float hval[TILE];
#pragma unroll
        for (int e = 0; e < TILE; e++) {
            float acc = bc;
            const float4* pa = (const float4*)sa[e];
#pragma unroll
            for (int k4 = 0; k4 < EDIM / 4; k4++) {
                float4 a = pa[k4];
                acc = fmaf(a.x, Wreg[4 * k4 + 0], acc);
                acc = fmaf(a.y, Wreg[4 * k4 + 1], acc);
                acc = fmaf(a.z, Wreg[4 * k4 + 2], acc);
                acc = fmaf(a.w, Wreg[4 * k4 + 3], acc);
            }
            float h = fmaxf(acc, 0.f);
            hval[e] = h;
            float s = h, s2 = h * h;
#pragma unroll
            for (int o = 16; o; o >>= 1) {
                s  += __shfl_xor_sync(0xFFFFFFFFu, s,  o);
                s2 += __shfl_xor_sync(0xFFFFFFFFu, s2, o);
            }
            if (lane == 0) { sred[e][0][warp] = s; sred[e][1][warp] = s2; }
        }
        __syncthreads();

        // ---- layernorm + write normalized features to smem ----
#pragma unroll
        for (int e = 0; e < TILE; e++) {
            float s  = sred[e][0][0] + sred[e][0][1] + sred[e][0][2] + sred[e][0][3];
            float s2 = sred[e][1][0] + sred[e][1][1] + sred[e][1][2] + sred[e][1][3];
            float mu  = s * (1.f / NDIM);
            float var = s2 * (1.f / NDIM) - mu * mu;
            float r   = rsqrtf(var + LN_EPS);
            sh[e][c]  = (hval[e] - mu) * r * gc + bec;
        }
        __syncthreads();

        // ---- vectorized scatter: 2*TILE rows, 4 rows per pass, float4 per lane ----
#pragma unroll
        for (int rr = 0; rr < (2 * TILE) / 4; rr++) {
            const int row   = rr * 4 + warp;
            const int e     = row & (TILE - 1);
            const int which = row >> 3;
            if (e < nE) {
                unsigned node = (unsigned)sidx[which][e];
                if (node < (unsigned)n_nodes) {
                    float* dst = out + (long long)node * NDIM + 4 * lane;
                    float4 v = ((float4*)sh[e])[lane];
                    asm volatile("red.global.add.v4.f32 [%0], {%1,%2,%3,%4};"
                                 :: "l"(dst), "f"(v.x), "f"(v.y), "f"(v.z), "f"(v.w)
                                 : "memory");
                }
            }
        }
        if (tid < 2 * TILE) {
            const int which = tid / TILE;
            const int e     = tid % TILE;
            if (e < nE) {
                unsigned node = (unsigned)sidx[which][e];
                if (node < (unsigned)n_nodes)
                    atomicAdd(&g_degree[node], 1.f);
            }
        }
        __syncthreads();   // smem reuse next tile
    }
}

__global__ void finalize_kernel(float4* __restrict__ out, int n_nodes) {
    const int total = n_nodes * (NDIM / 4);          // float4 count
    int i = blockIdx.x * blockDim.x + threadIdx.x;
    int stride = gridDim.x * blockDim.x;
    for (int j = i; j < total; j += stride) {
        int node = j >> 5;                           // j / (NDIM/4)
        float d = fmaxf(g_degree[node], 1.f);
        float inv = 1.f / d;
        float4 v = out[j];
        v.x *= inv; v.y *= inv; v.z *= inv; v.w *= inv;
        out[j] = v;
    }
}

extern "C" void kernel_launch(void* const* d_in, const int* in_sizes, int n_in,
                              void* d_out, int out_size) {
    // ---- resolve inputs by element count (order-permutation-proof) ----
    // edge_attr: largest (E*64, fp32). W: 64*128. edge_index: 2*E (int32!).
    // b, gamma, beta: NDIM each, in relative order. num_nodes: 1 element.
    int ia = 0;
    for (int i = 1; i < n_in; i++)
        if (in_sizes[i] > in_sizes[ia]) ia = i;
    const float* edge_attr = (const float*)d_in[ia];
    const int E = in_sizes[ia] / EDIM;

    const float *W = 0, *b = 0, *gma = 0, *bta = 0;
    const int* eidx = 0;
    for (int i = 0; i < n_in; i++) {
        if (i == ia) continue;
        int s = in_sizes[i];
        if (s == EDIM * NDIM)      W = (const float*)d_in[i];
        else if (s == 2 * E)       eidx = (const int*)d_in[i];
        else if (s == NDIM) {
            if (!b)        b   = (const float*)d_in[i];
            else if (!gma) gma = (const float*)d_in[i];
            else           bta = (const float*)d_in[i];
        }
    }
    float* out = (float*)d_out;
    int n_nodes = out_size / NDIM;
    if (n_nodes > MAXNODES) n_nodes = MAXNODES;

    // zero accumulators (out is poisoned; graph replays must restart from 0)
    zero_kernel<<<2048, 256>>>((float4*)out, out_size / 4, n_nodes);

    const int n_tiles = (E + TILE - 1) / TILE;
    int grid = 148 * 8;
    if (grid > n_tiles) grid = n_tiles;
    edge_kernel<<<grid, THREADS>>>(edge_attr, W, b, gma, bta, eidx, out, E, n_nodes);

    finalize_kernel<<<1024, 256>>>((float4*)out, n_nodes);
}